// round 15
// baseline (speedup 1.0000x reference)
#include <cuda_runtime.h>
#include <cuda_fp16.h>
#include <cstdint>
#include <cstddef>

// Problem constants
#define BATCH 4
#define NSEQ 2048
#define DIM 512
#define NHEAD 8
#define DHEAD 128
#define INNER 1024
#define MROWS (BATCH*NSEQ)  // 8192

#define WIN 16
#define TN 64

// ---------------- scratch (allocation-free rule) ----------------
// fp16 packed operands in m16n8k16 fragment order.
// A atom = 16x16 f16 = 512B: lane*16 -> [a0,a1,a2,a3]. B atom = 8x16 = 256B.
__device__ __align__(16) __half g_y[MROWS * INNER];     // gemm1 out, fp16 row-major
__device__ __align__(16) __half g_xpk[MROWS * DIM];
__device__ __align__(16) __half g_spk[MROWS * INNER];
__device__ __align__(16) __half g_wgpk[DIM * INNER];    // Wg^T packed
__device__ __align__(16) __half g_wopk[INNER * DIM];    // Wout^T packed

// ---------------- helpers ----------------
typedef unsigned long long ull;
__device__ __forceinline__ ull pack_dup(float a) {
    ull r; asm("mov.b64 %0, {%1, %1};" : "=l"(r) : "f"(a)); return r;
}
__device__ __forceinline__ void ffma2(ull& d, ull a, ull b) {
    asm("fma.rn.f32x2 %0, %1, %2, %0;" : "+l"(d) : "l"(a), "l"(b));
}
__device__ __forceinline__ void unpack2(ull v, float& lo, float& hi) {
    asm("mov.b64 {%0, %1}, %2;" : "=f"(lo), "=f"(hi) : "l"(v));
}
__device__ __forceinline__ uint32_t smem_to_u32(const void* p) {
    uint32_t a;
    asm("{ .reg .u64 t; cvta.to.shared.u64 t, %1; cvt.u32.u64 %0, t; }" : "=r"(a) : "l"(p));
    return a;
}
__device__ __forceinline__ void cp16(uint32_t dst, const void* src) {
    asm volatile("cp.async.cg.shared.global [%0], [%1], 16;" :: "r"(dst), "l"(src) : "memory");
}
#define CP_COMMIT() asm volatile("cp.async.commit_group;" ::: "memory")
#define CP_WAIT1()  asm volatile("cp.async.wait_group 1;" ::: "memory")

__device__ __forceinline__ void lds128(uint32_t addr, uint32_t* r) {
    asm volatile("ld.shared.v4.b32 {%0,%1,%2,%3}, [%4];"
                 : "=r"(r[0]), "=r"(r[1]), "=r"(r[2]), "=r"(r[3]) : "r"(addr));
}
__device__ __forceinline__ void lds64(uint32_t addr, uint32_t* r) {
    asm volatile("ld.shared.v2.b32 {%0,%1}, [%2];"
                 : "=r"(r[0]), "=r"(r[1]) : "r"(addr));
}
__device__ __forceinline__ void mma_f16(float* d, const uint32_t* a, const uint32_t* b) {
    asm volatile("mma.sync.aligned.m16n8k16.row.col.f32.f16.f16.f32 "
                 "{%0,%1,%2,%3}, {%4,%5,%6,%7}, {%8,%9}, {%0,%1,%2,%3};"
                 : "+f"(d[0]), "+f"(d[1]), "+f"(d[2]), "+f"(d[3])
                 : "r"(a[0]), "r"(a[1]), "r"(a[2]), "r"(a[3]), "r"(b[0]), "r"(b[1]));
}
__device__ __forceinline__ uint32_t h2u(float a, float b) {
    __half2 h = __floats2half2_rn(a, b);
    return *(uint32_t*)&h;
}

// ---------------------------------------------------------------------------
// fp16 GEMM (round-12 proven): C[M,N] = A[M,K] @ B^T, packed fragments.
// CTA 128x128, K-chunk 64 (4 k16), 8 warps (2m x 4n), warp tile 64x32.
// 3-stage cp.async pipeline. C written f32 or f16 (halfOut).
// ---------------------------------------------------------------------------
#define CTM 128
#define CTN 128
#define STG_A_BYTES 16384
#define STG_B_BYTES 16384
#define STAGE_BYTES (STG_A_BYTES + STG_B_BYTES)  // 32768
#define SMEM_GEMM (3 * STAGE_BYTES)              // 98304

__global__ __launch_bounds__(256, 2)
void gemm_f16(const __half* __restrict__ Apk, const __half* __restrict__ Bpk,
              void* __restrict__ Cv, int halfOut, int M, int N, int K) {
    extern __shared__ char smem[];
    const uint32_t sb = smem_to_u32(smem);
    const int tid = threadIdx.x;
    const int wid = tid >> 5;
    const int lane = tid & 31;
    const int row0 = blockIdx.y << 7;
    const int col0 = blockIdx.x << 7;
    const int kbT = K >> 4;
    const int mb0 = row0 >> 4;
    const int nb0 = col0 >> 3;

    const int wm = wid & 1;
    const int wn = wid >> 1;

    auto load_stage = [&](int buf, int kt) {
        const uint32_t st = sb + buf * STAGE_BYTES;
        const int kb0 = kt << 2;
#pragma unroll
        for (int r = 0; r < 4; r++) {
            const int i = tid + (r << 8);
            const int atomL = i >> 5;
            const int inner = (i & 31) << 4;
            const int mbL = atomL >> 2, kbL = atomL & 3;
            const size_t g = ((size_t)(mb0 + mbL) * kbT + kb0 + kbL) * 512 + inner;
            cp16(st + (atomL << 9) + inner, (const char*)Apk + g);
        }
#pragma unroll
        for (int r = 0; r < 4; r++) {
            const int i = tid + (r << 8);
            const int atomL = i >> 4;
            const int inner = (i & 15) << 4;
            const int nbL = atomL >> 2, kbL = atomL & 3;
            const size_t g = ((size_t)(nb0 + nbL) * kbT + kb0 + kbL) * 256 + inner;
            cp16(st + STG_A_BYTES + (atomL << 8) + inner, (const char*)Bpk + g);
        }
    };

    float d[4][4][4];
#pragma unroll
    for (int i = 0; i < 4; i++)
#pragma unroll
        for (int j = 0; j < 4; j++)
#pragma unroll
            for (int q = 0; q < 4; q++) d[i][j][q] = 0.f;

    const int KT = K >> 6;
    load_stage(0, 0); CP_COMMIT();
    load_stage(1, 1); CP_COMMIT();

    const uint32_t la16 = (uint32_t)lane << 4;
    const uint32_t la8  = (uint32_t)lane << 3;

    int cur = 0, nxt2 = 2;
    for (int kt = 0; kt < KT; kt++) {
        CP_WAIT1();
        __syncthreads();
        if (kt + 2 < KT) load_stage(nxt2, kt + 2);
        CP_COMMIT();

        const uint32_t st = sb + cur * STAGE_BYTES;
#pragma unroll
        for (int ki = 0; ki < 4; ki++) {
            uint32_t a[4][4], b[4][2];
#pragma unroll
            for (int mi = 0; mi < 4; mi++)
                lds128(st + (uint32_t)(((((wm << 2) + mi) << 2) + ki) << 9) + la16, a[mi]);
#pragma unroll
            for (int ni = 0; ni < 4; ni++)
                lds64(st + STG_A_BYTES
                      + (uint32_t)(((((wn << 2) + ni) << 2) + ki) << 8) + la8, b[ni]);
#pragma unroll
            for (int mi = 0; mi < 4; mi++)
#pragma unroll
                for (int ni = 0; ni < 4; ni++)
                    mma_f16(d[mi][ni], a[mi], b[ni]);
        }
        cur  = (cur == 2)  ? 0 : cur + 1;
        nxt2 = (nxt2 == 2) ? 0 : nxt2 + 1;
    }

    const int gr = lane >> 2;
    const int tg = lane & 3;
    if (halfOut) {
        __half* C = (__half*)Cv;
#pragma unroll
        for (int mi = 0; mi < 4; mi++) {
            const int r0 = row0 + (wm << 6) + (mi << 4) + gr;
#pragma unroll
            for (int ni = 0; ni < 4; ni++) {
                const int c = col0 + (wn << 5) + (ni << 3) + (tg << 1);
                *(uint32_t*)&C[(size_t)r0 * N + c]       = h2u(d[mi][ni][0], d[mi][ni][1]);
                *(uint32_t*)&C[(size_t)(r0 + 8) * N + c] = h2u(d[mi][ni][2], d[mi][ni][3]);
            }
        }
    } else {
        float* C = (float*)Cv;
#pragma unroll
        for (int mi = 0; mi < 4; mi++) {
            const int r0 = row0 + (wm << 6) + (mi << 4) + gr;
#pragma unroll
            for (int ni = 0; ni < 4; ni++) {
                const int c = col0 + (wn << 5) + (ni << 3) + (tg << 1);
                *(float2*)&C[(size_t)r0 * N + c]       = make_float2(d[mi][ni][0], d[mi][ni][1]);
                *(float2*)&C[(size_t)(r0 + 8) * N + c] = make_float2(d[mi][ni][2], d[mi][ni][3]);
            }
        }
    }
}

// ---------------------------------------------------------------------------
// merged pack: blocks [0,2048) pack x; [2048,2560) Wg^T; [2560,3072) Wout^T
// ---------------------------------------------------------------------------
__device__ __forceinline__ void pack_a_body(const float* src, __half* dst,
                                            int t, int M, int K) {
    const int kbT = K >> 4;
    const int atom = t >> 5;
    if (atom >= (M >> 4) * kbT) return;
    const int lane = t & 31;
    const int mb = atom / kbT, kb = atom % kbT;
    const int g = lane >> 2, tt = lane & 3;
    const int r0 = mb * 16 + g, r1 = r0 + 8;
    const int c0 = kb * 16 + tt * 2;
    const float2 v0 = *(const float2*)(src + (size_t)r0 * K + c0);
    const float2 v1 = *(const float2*)(src + (size_t)r1 * K + c0);
    const float2 v2 = *(const float2*)(src + (size_t)r0 * K + c0 + 8);
    const float2 v3 = *(const float2*)(src + (size_t)r1 * K + c0 + 8);
    uint4 o;
    o.x = h2u(v0.x, v0.y);
    o.y = h2u(v1.x, v1.y);
    o.z = h2u(v2.x, v2.y);
    o.w = h2u(v3.x, v3.y);
    *(uint4*)((char*)dst + (size_t)atom * 512 + lane * 16) = o;
}
__device__ __forceinline__ void pack_w_body(const float* W, __half* dst,
                                            int t, int K, int N) {
    const int kbT = K >> 4;
    const int atom = t >> 5;
    if (atom >= (N >> 3) * kbT) return;
    const int lane = t & 31;
    const int nb = atom / kbT, kb = atom % kbT;
    const int g = lane >> 2, tt = lane & 3;
    const int n = nb * 8 + g;
    const int k0 = kb * 16 + tt * 2;
    uint2 o;
    o.x = h2u(W[(size_t)k0 * N + n],       W[(size_t)(k0 + 1) * N + n]);
    o.y = h2u(W[(size_t)(k0 + 8) * N + n], W[(size_t)(k0 + 9) * N + n]);
    *(uint2*)((char*)dst + (size_t)atom * 256 + lane * 8) = o;
}

__global__ __launch_bounds__(256)
void pack_all(const float* __restrict__ x, const float* __restrict__ Wg,
              const float* __restrict__ Wout, __half* __restrict__ xpk,
              __half* __restrict__ wgpk, __half* __restrict__ wopk) {
    const int bid = blockIdx.x;
    if (bid < 2048) {
        pack_a_body(x, xpk, bid * 256 + threadIdx.x, MROWS, DIM);
    } else if (bid < 2560) {
        pack_w_body(Wg, wgpk, (bid - 2048) * 256 + threadIdx.x, DIM, INNER);
    } else {
        pack_w_body(Wout, wopk, (bid - 2560) * 256 + threadIdx.x, INNER, DIM);
    }
}

// ---------------------------------------------------------------------------
// Gaussian banded smoothing (WIN=16), row-normalized. Reads fp16 y, f32 math,
// writes s in packed fp16 A-fragment layout.
// Register-window version: thread = (channel-pair, 8-row group). Loads its
// 40-row y window into registers ONCE (40 LDS.64), then 33x8 stencil fully
// register-resident with ew hoisted (33 LDS.32). Arithmetic order identical
// to round 12 (j ascending per output) -> bit-identical results.
// ---------------------------------------------------------------------------
__global__ __launch_bounds__(256, 2)
void smooth_kernel(const __half* __restrict__ y, __half* __restrict__ spk,
                   const float* __restrict__ sigma) {
    __shared__ float yt[TN + 2 * WIN][64];
    __shared__ float ew[2 * WIN + 1];
    __shared__ float invZ[TN];

    const int n0 = blockIdx.x * TN;
    const int half = blockIdx.y;
    const int bh = blockIdx.z;
    const int b = bh >> 3;
    const int h = bh & 7;
    const int tid = threadIdx.x;

    const __half* ybase = y + (size_t)b * NSEQ * INNER + h * DHEAD + half * 64;
    for (int i = tid; i < (TN + 2 * WIN) * 8; i += 256) {
        const int r = i >> 3;
        const int c = (i & 7) << 3;
        const int m = n0 - WIN + r;
        float2 f0 = make_float2(0.f, 0.f), f1 = f0, f2 = f0, f3 = f0;
        if (m >= 0 && m < NSEQ) {
            const uint4 v = *(const uint4*)(ybase + (size_t)m * INNER + c);
            f0 = __half22float2(*(const __half2*)&v.x);
            f1 = __half22float2(*(const __half2*)&v.y);
            f2 = __half22float2(*(const __half2*)&v.z);
            f3 = __half22float2(*(const __half2*)&v.w);
        }
        *(float4*)&yt[r][c]     = make_float4(f0.x, f0.y, f1.x, f1.y);
        *(float4*)&yt[r][c + 4] = make_float4(f2.x, f2.y, f3.x, f3.y);
    }
    if (tid < 2 * WIN + 1) {
        const float sg = sigma[h];
        const float dd = (float)(tid - WIN);
        ew[tid] = __expf(-dd * dd / (2.f * sg * sg));
    }
    __syncthreads();
    if (tid < TN) {
        const int n = n0 + tid;
        float z = 0.f;
#pragma unroll
        for (int j = 0; j <= 2 * WIN; j++) {
            const int m = n - WIN + j;
            if (m >= 0 && m < NSEQ) z += ew[j];
        }
        invZ[tid] = 1.f / z;
    }
    __syncthreads();

    const int cp = tid & 31;     // channel pair
    const int tg = tid >> 5;     // 0..7, 8 t-rows each

    // load the 40-row window for this (tg, cp) into registers
    ull yw[40];
#pragma unroll
    for (int r = 0; r < 40; r++)
        yw[r] = *(const ull*)&yt[tg * 8 + r][cp << 1];

    // stencil: acc[k] = sum_j ew[j] * yw[k + j]   (j ascending, as before)
    ull acc[8];
#pragma unroll
    for (int k = 0; k < 8; k++) acc[k] = 0ULL;
#pragma unroll
    for (int j = 0; j <= 2 * WIN; j++) {
        const ull w = pack_dup(ew[j]);
#pragma unroll
        for (int k = 0; k < 8; k++)
            ffma2(acc[k], w, yw[k + j]);
    }

    const int c0 = h * DHEAD + half * 64 + (cp << 1);
    const int kbG = c0 >> 4;
    const int k16 = c0 & 15;
    const int tt = (k16 >> 1) & 3;
    const int khalf = k16 >> 3;
#pragma unroll
    for (int k = 0; k < 8; k++) {
        const int t = tg * 8 + k;
        float ax, ay;
        unpack2(acc[k], ax, ay);
        const float iz = invZ[t];
        const uint32_t pr = h2u(ax * iz, ay * iz);
        const int m = b * NSEQ + n0 + t;
        const int mb = m >> 4;
        const int r16 = m & 15;
        const int g = r16 & 7;
        const int up = r16 >> 3;
        const int lanef = (g << 2) + tt;
        const int reg = (khalf << 1) + up;
        const size_t off = ((size_t)mb * (INNER / 16) + kbG) * 512 + lanef * 16 + reg * 4;
        *(uint32_t*)((char*)spk + off) = pr;
    }
}

// ---------------------------------------------------------------------------
extern "C" void kernel_launch(void* const* d_in, const int* in_sizes, int n_in,
                              void* d_out, int out_size) {
    const float* x     = (const float*)d_in[0];
    const float* Wg    = (const float*)d_in[1];
    const float* Wout  = (const float*)d_in[2];
    const float* sigma = (const float*)d_in[3];
    float* out = (float*)d_out;

    __half *y, *xpk, *spk, *wgpk, *wopk;
    cudaGetSymbolAddress((void**)&y,    g_y);
    cudaGetSymbolAddress((void**)&xpk,  g_xpk);
    cudaGetSymbolAddress((void**)&spk,  g_spk);
    cudaGetSymbolAddress((void**)&wgpk, g_wgpk);
    cudaGetSymbolAddress((void**)&wopk, g_wopk);

    cudaFuncSetAttribute(gemm_f16, cudaFuncAttributeMaxDynamicSharedMemorySize, SMEM_GEMM);

    // prep: pack x, Wg^T, Wout^T to fp16 fragment layouts (one launch)
    pack_all<<<3072, 256>>>(x, Wg, Wout, xpk, wgpk, wopk);

    // GEMM1: y[8192,1024](fp16) = x @ Wg
    gemm_f16<<<dim3(INNER / CTN, MROWS / CTM), 256, SMEM_GEMM>>>(
        xpk, wgpk, y, 1, MROWS, INNER, DIM);

    // banded Gaussian attention -> s (packed fp16)
    smooth_kernel<<<dim3(NSEQ / TN, 2, BATCH * NHEAD), 256>>>(y, spk, sigma);

    // GEMM2: out[8192,512](f32) = s @ Wout
    gemm_f16<<<dim3(DIM / CTN, MROWS / CTM), 256, SMEM_GEMM>>>(
        spk, wopk, out, 0, MROWS, DIM, INNER);
}

// round 17
// speedup vs baseline: 1.1135x; 1.1135x over previous
#include <cuda_runtime.h>
#include <cuda_fp16.h>
#include <cstdint>
#include <cstddef>

// Problem constants
#define BATCH 4
#define NSEQ 2048
#define DIM 512
#define NHEAD 8
#define DHEAD 128
#define INNER 1024
#define MROWS (BATCH*NSEQ)  // 8192

#define WIN 16

// ---------------- scratch (allocation-free rule) ----------------
__device__ __align__(16) __half g_y[MROWS * INNER];     // gemm1 out, fp16 row-major
__device__ __align__(16) __half g_xpk[MROWS * DIM];
__device__ __align__(16) __half g_spk[MROWS * INNER];
__device__ __align__(16) __half g_wgpk[DIM * INNER];    // Wg^T packed
__device__ __align__(16) __half g_wopk[INNER * DIM];    // Wout^T packed
__device__ __align__(16) uint8_t g_gpk[8 * 24 * 512];   // Gauss band A-fragments / head

// ---------------- helpers ----------------
typedef unsigned long long ull;
__device__ __forceinline__ uint32_t smem_to_u32(const void* p) {
    uint32_t a;
    asm("{ .reg .u64 t; cvta.to.shared.u64 t, %1; cvt.u32.u64 %0, t; }" : "=r"(a) : "l"(p));
    return a;
}
__device__ __forceinline__ void cp16(uint32_t dst, const void* src) {
    asm volatile("cp.async.cg.shared.global [%0], [%1], 16;" :: "r"(dst), "l"(src) : "memory");
}
#define CP_COMMIT() asm volatile("cp.async.commit_group;" ::: "memory")
#define CP_WAIT1()  asm volatile("cp.async.wait_group 1;" ::: "memory")
#define CP_WAIT0()  asm volatile("cp.async.wait_group 0;" ::: "memory")

__device__ __forceinline__ void lds128(uint32_t addr, uint32_t* r) {
    asm volatile("ld.shared.v4.b32 {%0,%1,%2,%3}, [%4];"
                 : "=r"(r[0]), "=r"(r[1]), "=r"(r[2]), "=r"(r[3]) : "r"(addr));
}
__device__ __forceinline__ void lds64(uint32_t addr, uint32_t* r) {
    asm volatile("ld.shared.v2.b32 {%0,%1}, [%2];"
                 : "=r"(r[0]), "=r"(r[1]) : "r"(addr));
}
__device__ __forceinline__ void ldsm_x4_t(uint32_t addr, uint32_t& r0, uint32_t& r1,
                                          uint32_t& r2, uint32_t& r3) {
    asm volatile("ldmatrix.sync.aligned.m8n8.x4.trans.shared.b16 {%0,%1,%2,%3}, [%4];"
                 : "=r"(r0), "=r"(r1), "=r"(r2), "=r"(r3) : "r"(addr));
}
__device__ __forceinline__ void mma_f16(float* d, const uint32_t* a, const uint32_t* b) {
    asm volatile("mma.sync.aligned.m16n8k16.row.col.f32.f16.f16.f32 "
                 "{%0,%1,%2,%3}, {%4,%5,%6,%7}, {%8,%9}, {%0,%1,%2,%3};"
                 : "+f"(d[0]), "+f"(d[1]), "+f"(d[2]), "+f"(d[3])
                 : "r"(a[0]), "r"(a[1]), "r"(a[2]), "r"(a[3]), "r"(b[0]), "r"(b[1]));
}
__device__ __forceinline__ uint32_t h2u(float a, float b) {
    __half2 h = __floats2half2_rn(a, b);
    return *(uint32_t*)&h;
}

// ---------------------------------------------------------------------------
// fp16 GEMM (round-12 proven): C[M,N] = A[M,K] @ B^T, packed fragments.
// ---------------------------------------------------------------------------
#define CTM 128
#define CTN 128
#define STG_A_BYTES 16384
#define STG_B_BYTES 16384
#define STAGE_BYTES (STG_A_BYTES + STG_B_BYTES)
#define SMEM_GEMM (3 * STAGE_BYTES)              // 98304

__global__ __launch_bounds__(256, 2)
void gemm_f16(const __half* __restrict__ Apk, const __half* __restrict__ Bpk,
              void* __restrict__ Cv, int halfOut, int M, int N, int K) {
    extern __shared__ char smem[];
    const uint32_t sb = smem_to_u32(smem);
    const int tid = threadIdx.x;
    const int wid = tid >> 5;
    const int lane = tid & 31;
    const int row0 = blockIdx.y << 7;
    const int col0 = blockIdx.x << 7;
    const int kbT = K >> 4;
    const int mb0 = row0 >> 4;
    const int nb0 = col0 >> 3;

    const int wm = wid & 1;
    const int wn = wid >> 1;

    auto load_stage = [&](int buf, int kt) {
        const uint32_t st = sb + buf * STAGE_BYTES;
        const int kb0 = kt << 2;
#pragma unroll
        for (int r = 0; r < 4; r++) {
            const int i = tid + (r << 8);
            const int atomL = i >> 5;
            const int inner = (i & 31) << 4;
            const int mbL = atomL >> 2, kbL = atomL & 3;
            const size_t g = ((size_t)(mb0 + mbL) * kbT + kb0 + kbL) * 512 + inner;
            cp16(st + (atomL << 9) + inner, (const char*)Apk + g);
        }
#pragma unroll
        for (int r = 0; r < 4; r++) {
            const int i = tid + (r << 8);
            const int atomL = i >> 4;
            const int inner = (i & 15) << 4;
            const int nbL = atomL >> 2, kbL = atomL & 3;
            const size_t g = ((size_t)(nb0 + nbL) * kbT + kb0 + kbL) * 256 + inner;
            cp16(st + STG_A_BYTES + (atomL << 8) + inner, (const char*)Bpk + g);
        }
    };

    float d[4][4][4];
#pragma unroll
    for (int i = 0; i < 4; i++)
#pragma unroll
        for (int j = 0; j < 4; j++)
#pragma unroll
            for (int q = 0; q < 4; q++) d[i][j][q] = 0.f;

    const int KT = K >> 6;
    load_stage(0, 0); CP_COMMIT();
    load_stage(1, 1); CP_COMMIT();

    const uint32_t la16 = (uint32_t)lane << 4;
    const uint32_t la8  = (uint32_t)lane << 3;

    int cur = 0, nxt2 = 2;
    for (int kt = 0; kt < KT; kt++) {
        CP_WAIT1();
        __syncthreads();
        if (kt + 2 < KT) load_stage(nxt2, kt + 2);
        CP_COMMIT();

        const uint32_t st = sb + cur * STAGE_BYTES;
#pragma unroll
        for (int ki = 0; ki < 4; ki++) {
            uint32_t a[4][4], b[4][2];
#pragma unroll
            for (int mi = 0; mi < 4; mi++)
                lds128(st + (uint32_t)(((((wm << 2) + mi) << 2) + ki) << 9) + la16, a[mi]);
#pragma unroll
            for (int ni = 0; ni < 4; ni++)
                lds64(st + STG_A_BYTES
                      + (uint32_t)(((((wn << 2) + ni) << 2) + ki) << 8) + la8, b[ni]);
#pragma unroll
            for (int mi = 0; mi < 4; mi++)
#pragma unroll
                for (int ni = 0; ni < 4; ni++)
                    mma_f16(d[mi][ni], a[mi], b[ni]);
        }
        cur  = (cur == 2)  ? 0 : cur + 1;
        nxt2 = (nxt2 == 2) ? 0 : nxt2 + 1;
    }

    const int gr = lane >> 2;
    const int tg = lane & 3;
    if (halfOut) {
        __half* C = (__half*)Cv;
#pragma unroll
        for (int mi = 0; mi < 4; mi++) {
            const int r0 = row0 + (wm << 6) + (mi << 4) + gr;
#pragma unroll
            for (int ni = 0; ni < 4; ni++) {
                const int c = col0 + (wn << 5) + (ni << 3) + (tg << 1);
                *(uint32_t*)&C[(size_t)r0 * N + c]       = h2u(d[mi][ni][0], d[mi][ni][1]);
                *(uint32_t*)&C[(size_t)(r0 + 8) * N + c] = h2u(d[mi][ni][2], d[mi][ni][3]);
            }
        }
    } else {
        float* C = (float*)Cv;
#pragma unroll
        for (int mi = 0; mi < 4; mi++) {
            const int r0 = row0 + (wm << 6) + (mi << 4) + gr;
#pragma unroll
            for (int ni = 0; ni < 4; ni++) {
                const int c = col0 + (wn << 5) + (ni << 3) + (tg << 1);
                *(float2*)&C[(size_t)r0 * N + c]       = make_float2(d[mi][ni][0], d[mi][ni][1]);
                *(float2*)&C[(size_t)(r0 + 8) * N + c] = make_float2(d[mi][ni][2], d[mi][ni][3]);
            }
        }
    }
}

// ---------------------------------------------------------------------------
// merged pack: [0,2048) x; [2048,2560) Wg^T; [2560,3072) Wout^T;
// [3072,3096) Gauss band matrices per head -> A-fragment atoms.
// ---------------------------------------------------------------------------
__device__ __forceinline__ void pack_a_body(const float* src, __half* dst,
                                            int t, int M, int K) {
    const int kbT = K >> 4;
    const int atom = t >> 5;
    if (atom >= (M >> 4) * kbT) return;
    const int lane = t & 31;
    const int mb = atom / kbT, kb = atom % kbT;
    const int g = lane >> 2, tt = lane & 3;
    const int r0 = mb * 16 + g, r1 = r0 + 8;
    const int c0 = kb * 16 + tt * 2;
    const float2 v0 = *(const float2*)(src + (size_t)r0 * K + c0);
    const float2 v1 = *(const float2*)(src + (size_t)r1 * K + c0);
    const float2 v2 = *(const float2*)(src + (size_t)r0 * K + c0 + 8);
    const float2 v3 = *(const float2*)(src + (size_t)r1 * K + c0 + 8);
    uint4 o;
    o.x = h2u(v0.x, v0.y);
    o.y = h2u(v1.x, v1.y);
    o.z = h2u(v2.x, v2.y);
    o.w = h2u(v3.x, v3.y);
    *(uint4*)((char*)dst + (size_t)atom * 512 + lane * 16) = o;
}
__device__ __forceinline__ void pack_w_body(const float* W, __half* dst,
                                            int t, int K, int N) {
    const int kbT = K >> 4;
    const int atom = t >> 5;
    if (atom >= (N >> 3) * kbT) return;
    const int lane = t & 31;
    const int nb = atom / kbT, kb = atom % kbT;
    const int g = lane >> 2, tt = lane & 3;
    const int n = nb * 8 + g;
    const int k0 = kb * 16 + tt * 2;
    uint2 o;
    o.x = h2u(W[(size_t)k0 * N + n],       W[(size_t)(k0 + 1) * N + n]);
    o.y = h2u(W[(size_t)(k0 + 8) * N + n], W[(size_t)(k0 + 9) * N + n]);
    *(uint2*)((char*)dst + (size_t)atom * 256 + lane * 8) = o;
}

__device__ __forceinline__ float gaussw(int tp, int j, float inv2s2) {
    const int dd = j - tp - WIN;
    return (dd >= -WIN && dd <= WIN) ? __expf((float)(dd * dd) * inv2s2) : 0.f;
}

__global__ __launch_bounds__(256)
void pack_all(const float* __restrict__ x, const float* __restrict__ Wg,
              const float* __restrict__ Wout, const float* __restrict__ sigma,
              __half* __restrict__ xpk, __half* __restrict__ wgpk,
              __half* __restrict__ wopk, uint8_t* __restrict__ gpk) {
    const int bid = blockIdx.x;
    if (bid < 2048) {
        pack_a_body(x, xpk, bid * 256 + threadIdx.x, MROWS, DIM);
    } else if (bid < 2560) {
        pack_w_body(Wg, wgpk, (bid - 2048) * 256 + threadIdx.x, DIM, INNER);
    } else if (bid < 3072) {
        pack_w_body(Wout, wopk, (bid - 2560) * 256 + threadIdx.x, INNER, DIM);
    } else {
        // Gauss band fragments: G_h[64 t'][96 j], A-atom layout (4 mb x 6 kb)
        const int t = (bid - 3072) * 256 + threadIdx.x;   // 0..6143
        const int lane = t & 31;
        const int atomAll = t >> 5;                        // 0..191
        const int h = atomAll / 24;
        const int atom = atomAll % 24;
        const int mb = atom / 6, kb = atom % 6;
        const int g = lane >> 2, tt = lane & 3;
        const float sg = sigma[h];
        const float inv2s2 = -1.f / (2.f * sg * sg);
        const int r0 = mb * 16 + g, r1 = r0 + 8;
        const int j0 = kb * 16 + tt * 2;
        uint4 o;
        o.x = h2u(gaussw(r0, j0, inv2s2),     gaussw(r0, j0 + 1, inv2s2));
        o.y = h2u(gaussw(r1, j0, inv2s2),     gaussw(r1, j0 + 1, inv2s2));
        o.z = h2u(gaussw(r0, j0 + 8, inv2s2), gaussw(r0, j0 + 9, inv2s2));
        o.w = h2u(gaussw(r1, j0 + 8, inv2s2), gaussw(r1, j0 + 9, inv2s2));
        *(uint4*)(gpk + (size_t)(h * 24 + atom) * 512 + lane * 16) = o;
    }
}

// ---------------------------------------------------------------------------
// Tensor-core Gaussian smoothing: per (b,h,t-block) S[64,128] = G[64,96] @ Y[96,128].
// G from pre-packed A-fragments; Y fragments via ldmatrix.x4.trans from the
// row-major fp16 y tile in SMEM. Row-normalize by f32 invZ in epilogue; store
// s in packed A-fragment layout for GEMM2.
// ---------------------------------------------------------------------------
#define G_OFF 0
#define G_BYTES 12288
#define YS_OFF 12288
#define YS_STRIDE 272                   // 128 f16 (256B) + 16B pad
#define YS_BYTES (96 * YS_STRIDE)       // 26112
#define IZ_OFF (YS_OFF + YS_BYTES)      // 38400
#define SM_SMEM (IZ_OFF + 256)          // 38656

__global__ __launch_bounds__(256, 2)
void smooth_mma(const __half* __restrict__ y, __half* __restrict__ spk,
                const float* __restrict__ sigma) {
    extern __shared__ char smem[];
    const uint32_t sb = smem_to_u32(smem);
    const int tid = threadIdx.x;
    const int wid = tid >> 5;
    const int lane = tid & 31;
    const int t0 = blockIdx.x << 6;
    const int bh = blockIdx.y;
    const int b = bh >> 3;
    const int h = bh & 7;

    // load G fragments (12KB = 768 chunks)
#pragma unroll
    for (int r = 0; r < 3; r++) {
        const int idx = tid + (r << 8);
        cp16(sb + G_OFF + idx * 16, g_gpk + (size_t)h * G_BYTES + idx * 16);
    }
    // load y tile: 96 rows x 128 ch fp16 = 96 x 16 chunks of 16B = 1536 chunks
#pragma unroll
    for (int r = 0; r < 6; r++) {
        const int idx = tid + (r << 8);
        const int row = idx >> 4;
        const int ch8 = (idx & 15) << 3;     // 0,8,...,120
        const int tg2 = t0 + row - WIN;
        const uint32_t dst = sb + YS_OFF + row * YS_STRIDE + ch8 * 2;
        if (tg2 >= 0 && tg2 < NSEQ) {
            cp16(dst, y + ((size_t)b * NSEQ + tg2) * INNER + h * DHEAD + ch8);
        } else {
            asm volatile("st.shared.v4.b32 [%0], {%1,%1,%1,%1};" :: "r"(dst), "r"(0u));
        }
    }
    CP_COMMIT();
    // invZ (f32, exact weights)
    if (tid < 64) {
        const float sg = sigma[h];
        const float inv2s2 = -1.f / (2.f * sg * sg);
        const int n = t0 + tid;
        float z = 0.f;
#pragma unroll
        for (int j = 0; j <= 2 * WIN; j++) {
            const int m = n - WIN + j;
            if (m >= 0 && m < NSEQ) {
                const float dd = (float)(j - WIN);
                z += __expf(dd * dd * inv2s2);
            }
        }
        *(float*)(smem + IZ_OFF + tid * 4) = 1.f / z;
    }
    CP_WAIT0();
    __syncthreads();

    const int wm = wid & 1;     // 2 m-warps x 32 t-rows
    const int wn = wid >> 1;    // 4 n-warps x 32 channels

    float d[2][4][4];
#pragma unroll
    for (int i = 0; i < 2; i++)
#pragma unroll
        for (int j = 0; j < 4; j++)
#pragma unroll
            for (int q = 0; q < 4; q++) d[i][j][q] = 0.f;

    const int q4 = lane >> 3;           // ldmatrix matrix id
    const int r8 = lane & 7;
    const uint32_t la16 = (uint32_t)lane << 4;

#pragma unroll
    for (int ki = 0; ki < 6; ki++) {
        uint32_t a[2][4], bf[4][2];
#pragma unroll
        for (int mi = 0; mi < 2; mi++)
            lds128(sb + G_OFF + (uint32_t)((((wm << 1) + mi) * 6 + ki) << 9) + la16, a[mi]);
#pragma unroll
        for (int pair = 0; pair < 2; pair++) {
            const int cc = (wn << 5) + (pair << 4) + ((q4 >> 1) << 3);
            const int krow = (ki << 4) + ((q4 & 1) << 3) + r8;
            const uint32_t ad = sb + YS_OFF + krow * YS_STRIDE + cc * 2;
            ldsm_x4_t(ad, bf[pair * 2][0], bf[pair * 2][1],
                          bf[pair * 2 + 1][0], bf[pair * 2 + 1][1]);
        }
#pragma unroll
        for (int mi = 0; mi < 2; mi++)
#pragma unroll
            for (int ni = 0; ni < 4; ni++)
                mma_f16(d[mi][ni], a[mi], bf[ni]);
    }

    // epilogue: normalize + store to spk fragment layout
    const int gr = lane >> 2;
    const int tg = lane & 3;
#pragma unroll
    for (int mi = 0; mi < 2; mi++) {
        const int tl0 = (wm << 5) + (mi << 4) + gr;      // local t (and +8)
#pragma unroll
        for (int ni = 0; ni < 4; ni++) {
            const int cl = (wn << 5) + (ni << 3) + (tg << 1);
            const int c0g = h * DHEAD + cl;
            const int kbG = c0g >> 4;
            const int k16 = c0g & 15;
            const int tt = (k16 >> 1) & 3;
            const int khalf = k16 >> 3;
#pragma unroll
            for (int up2 = 0; up2 < 2; up2++) {
                const int rl = tl0 + up2 * 8;
                const float iz = *(const float*)(smem + IZ_OFF + rl * 4);
                const uint32_t pr = h2u(d[mi][ni][up2 * 2] * iz,
                                        d[mi][ni][up2 * 2 + 1] * iz);
                const int m = b * NSEQ + t0 + rl;
                const int mb = m >> 4;
                const int r16 = m & 15;
                const int g = r16 & 7;
                const int up = r16 >> 3;
                const int lanef = (g << 2) + tt;
                const int reg = (khalf << 1) + up;
                const size_t off = ((size_t)mb * (INNER / 16) + kbG) * 512
                                 + lanef * 16 + reg * 4;
                *(uint32_t*)((char*)spk + off) = pr;
            }
        }
    }
}

// ---------------------------------------------------------------------------
extern "C" void kernel_launch(void* const* d_in, const int* in_sizes, int n_in,
                              void* d_out, int out_size) {
    const float* x     = (const float*)d_in[0];
    const float* Wg    = (const float*)d_in[1];
    const float* Wout  = (const float*)d_in[2];
    const float* sigma = (const float*)d_in[3];
    float* out = (float*)d_out;

    __half *y, *xpk, *spk, *wgpk, *wopk;
    uint8_t* gpk;
    cudaGetSymbolAddress((void**)&y,    g_y);
    cudaGetSymbolAddress((void**)&xpk,  g_xpk);
    cudaGetSymbolAddress((void**)&spk,  g_spk);
    cudaGetSymbolAddress((void**)&wgpk, g_wgpk);
    cudaGetSymbolAddress((void**)&wopk, g_wopk);
    cudaGetSymbolAddress((void**)&gpk,  g_gpk);

    cudaFuncSetAttribute(gemm_f16, cudaFuncAttributeMaxDynamicSharedMemorySize, SMEM_GEMM);
    cudaFuncSetAttribute(smooth_mma, cudaFuncAttributeMaxDynamicSharedMemorySize, SM_SMEM);

    // prep: pack x, Wg^T, Wout^T, Gauss bands (one launch)
    pack_all<<<3096, 256>>>(x, Wg, Wout, sigma, xpk, wgpk, wopk, gpk);

    // GEMM1: y[8192,1024](fp16) = x @ Wg
    gemm_f16<<<dim3(INNER / CTN, MROWS / CTM), 256, SMEM_GEMM>>>(
        xpk, wgpk, y, 1, MROWS, INNER, DIM);

    // banded Gaussian attention on tensor cores -> s (packed fp16 fragments)
    smooth_mma<<<dim3(NSEQ / 64, BATCH * NHEAD), 256, SM_SMEM>>>(y, spk, sigma);

    // GEMM2: out[8192,512](f32) = s @ Wout
    gemm_f16<<<dim3(DIM / CTN, MROWS / CTM), 256, SMEM_GEMM>>>(
        spk, wopk, out, 0, MROWS, DIM, INNER);
}